// round 8
// baseline (speedup 1.0000x reference)
#include <cuda_runtime.h>
#include <math.h>

// Rotated-IoU loss, one thread per pair. Reference decision structure
// (rel_err 4.96e-4 across R1/R6/R7). Ordering stage is now a Batcher
// odd-even mergesort network over 16 register-resident (key,x,y) triples:
// no rank scan, no dynamic scatter, no local-memory sort traffic.
// Invalid slots carry key=1e9 (the reference's sentinel); after sorting,
// invalid slots are padded with slot 0, reproducing the reference's
// pad-with-vs[0] + roll shoelace exactly (pad crosses are identically 0).

__device__ __forceinline__ float pseudo_angle(float x, float y)
{
    float d = fabsf(x) + fabsf(y);
    float r = __fdividef(y, d);
    r = (d > 0.f) ? r : 0.f;
    return (x >= 0.f) ? r : ((y >= 0.f) ? 2.f - r : -2.f - r);
}

__global__ void __launch_bounds__(256)
riou_kernel(const float* __restrict__ pred,
            const float* __restrict__ tgt,
            float* __restrict__ out, int n)
{
    int i = blockIdx.x * blockDim.x + threadIdx.x;
    if (i >= n) return;

    const float2* pp = reinterpret_cast<const float2*>(pred) + (size_t)i * 3;
    const float2* tp = reinterpret_cast<const float2*>(tgt)  + (size_t)i * 3;
    float2 a0 = pp[0], a1 = pp[1], a2 = pp[2];
    float2 b0 = tp[0], b1 = tp[1], b2 = tp[2];

    const float x1c = a0.x, y1c = a0.y, w1 = a1.x, h1 = a1.y;
    const float x2c = b0.x, y2c = b0.y, w2 = b1.x, h2 = b1.y;

    float inv1 = rsqrtf(a2.x * a2.x + a2.y * a2.y);
    float s1 = a2.x * inv1, c1 = a2.y * inv1;
    float inv2 = rsqrtf(b2.x * b2.x + b2.y * b2.y);
    float s2 = b2.x * inv2, c2 = b2.y * inv2;

    const float dxv[4] = {0.5f, -0.5f, -0.5f, 0.5f};
    const float dyv[4] = {0.5f, 0.5f, -0.5f, -0.5f};
    float c1x[4], c1y[4], c2x[4], c2y[4];
#pragma unroll
    for (int j = 0; j < 4; j++) {
        float cx = dxv[j] * w1, cy = dyv[j] * h1;
        c1x[j] = cx * c1 - cy * s1 + x1c;
        c1y[j] = cx * s1 + cy * c1 + y1c;
    }
#pragma unroll
    for (int j = 0; j < 4; j++) {
        float cx = dxv[j] * w2, cy = dyv[j] * h2;
        c2x[j] = cx * c2 - cy * s2 + x2c;
        c2y[j] = cx * s2 + cy * c2 + y2c;
    }

    // ---- gather valid candidate vertices (compacted) ----
    float2 v[16];
    int    k = 0;
    float  sumx = 0.f, sumy = 0.f;
    const float eps = 1e-6f;

    {
        float ax = c2x[0], ay = c2y[0];
        float abx = c2x[1] - ax, aby = c2y[1] - ay;
        float adx = c2x[3] - ax, ady = c2y[3] - ay;
        float den_ab = abx * abx + aby * aby;
        float den_ad = adx * adx + ady * ady;
        float lo_ab = -eps * den_ab, hi_ab = (1.f + eps) * den_ab;
        float lo_ad = -eps * den_ad, hi_ad = (1.f + eps) * den_ad;
#pragma unroll
        for (int j = 0; j < 4; j++) {
            float amx = c1x[j] - ax, amy = c1y[j] - ay;
            float d_ab = abx * amx + aby * amy;
            float d_ad = adx * amx + ady * amy;
            if (d_ab > lo_ab && d_ab < hi_ab && d_ad > lo_ad && d_ad < hi_ad) {
                v[k] = make_float2(c1x[j], c1y[j]);
                sumx += c1x[j]; sumy += c1y[j];
                k++;
            }
        }
    }
    {
        float ax = c1x[0], ay = c1y[0];
        float abx = c1x[1] - ax, aby = c1y[1] - ay;
        float adx = c1x[3] - ax, ady = c1y[3] - ay;
        float den_ab = abx * abx + aby * aby;
        float den_ad = adx * adx + ady * ady;
        float lo_ab = -eps * den_ab, hi_ab = (1.f + eps) * den_ab;
        float lo_ad = -eps * den_ad, hi_ad = (1.f + eps) * den_ad;
#pragma unroll
        for (int j = 0; j < 4; j++) {
            float amx = c2x[j] - ax, amy = c2y[j] - ay;
            float d_ab = abx * amx + aby * amy;
            float d_ad = adx * amx + ady * amy;
            if (d_ab > lo_ab && d_ab < hi_ab && d_ad > lo_ad && d_ad < hi_ad) {
                v[k] = make_float2(c2x[j], c2y[j]);
                sumx += c2x[j]; sumy += c2y[j];
                k++;
            }
        }
    }
#pragma unroll
    for (int e1 = 0; e1 < 4; e1++) {
        float X1 = c1x[e1], Y1 = c1y[e1];
        float X2 = c1x[(e1 + 1) & 3], Y2 = c1y[(e1 + 1) & 3];
        float ex = X2 - X1, ey = Y2 - Y1;
#pragma unroll
        for (int e2 = 0; e2 < 4; e2++) {
            float X3 = c2x[e2], Y3 = c2y[e2];
            float X4 = c2x[(e2 + 1) & 3], Y4 = c2y[(e2 + 1) & 3];
            float gx = X4 - X3, gy = Y4 - Y3;
            float num_t = ex * (Y3 - Y1) - ey * (X3 - X1);
            float den   = ex * (Y3 - Y4) - ey * (X3 - X4);
            float num_u = gx * (Y1 - Y3) - gy * (X1 - X3);
            float den_u = -den;
            bool vt = (den > 0.f) ? (num_t > 0.f && num_t < den)
                                  : (den < 0.f && num_t < 0.f && num_t > den);
            bool vu = (den_u > 0.f) ? (num_u > 0.f && num_u < den_u)
                                    : (den_u < 0.f && num_u < 0.f && num_u > den_u);
            if (vt && vu) {
                float t = __fdividef(num_t, den);
                float ix = X1 + t * ex, iy = Y1 + t * ey;
                v[k] = make_float2(ix, iy);
                sumx += ix; sumy += iy;
                k++;
            }
        }
    }

    // ---- static readback: centered coords + sort keys (register triples) ----
    float invk = __fdividef(1.f, (float)(k > 0 ? k : 1));
    float meanx = sumx * invk, meany = sumy * invk;

    float key[16], sx[16], sy[16];
#pragma unroll
    for (int j = 0; j < 16; j++) {
        float vx = v[j].x - meanx, vy = v[j].y - meany;
        sx[j] = vx; sy[j] = vy;
        float a = pseudo_angle(vx, vy);
        key[j] = (j < k) ? a : 1e9f;
    }

    // ---- Batcher odd-even mergesort network, n=16 (63 compare-exchanges) ----
#pragma unroll
    for (int p = 1; p < 16; p <<= 1) {
#pragma unroll
        for (int q = p; q >= 1; q >>= 1) {
#pragma unroll
            for (int j = (q % p); j + q < 16; j += 2 * q) {
#pragma unroll
                for (int m = 0; m < q; m++) {
                    int a = j + m, b = j + m + q;
                    if (b < 16 && (a / (2 * p)) == (b / (2 * p))) {
                        bool sw = key[a] > key[b];
                        float tk = key[a];
                        key[a] = sw ? key[b] : tk;  key[b] = sw ? tk : key[b];
                        float tx = sx[a];
                        sx[a] = sw ? sx[b] : tx;    sx[b] = sw ? tx : sx[b];
                        float ty = sy[a];
                        sy[a] = sw ? sy[b] : ty;    sy[b] = sw ? ty : sy[b];
                    }
                }
            }
        }
    }

    // ---- pad invalid slots with slot 0, fixed shoelace with wrap ----
    float p0x = sx[0], p0y = sy[0];
    float qx[16], qy[16];
#pragma unroll
    for (int j = 0; j < 16; j++) {
        bool valid = key[j] < 1e8f;
        qx[j] = valid ? sx[j] : p0x;
        qy[j] = valid ? sy[j] : p0y;
    }
    float cr = 0.f;
#pragma unroll
    for (int j = 0; j < 16; j++) {
        int jn = (j + 1) & 15;
        cr += qx[j] * qy[jn] - qy[j] * qx[jn];
    }
    cr = (k > 0) ? cr : 0.f;   // k==0: slots hold garbage; reference gives 0
    float inter = 0.5f * fabsf(cr);

    // ---- enclosing box + loss ----
    float xmin = c1x[0], xmax = c1x[0], ymin = c1y[0], ymax = c1y[0];
#pragma unroll
    for (int j = 1; j < 4; j++) {
        xmin = fminf(xmin, c1x[j]); xmax = fmaxf(xmax, c1x[j]);
        ymin = fminf(ymin, c1y[j]); ymax = fmaxf(ymax, c1y[j]);
    }
#pragma unroll
    for (int j = 0; j < 4; j++) {
        xmin = fminf(xmin, c2x[j]); xmax = fmaxf(xmax, c2x[j]);
        ymin = fminf(ymin, c2y[j]); ymax = fmaxf(ymax, c2y[j]);
    }
    float wc = xmax - xmin, hc = ymax - ymin;
    float c2diag = wc * wc + hc * hc;
    float ddx = x1c - x2c, ddy = y1c - y2c;
    float d2 = ddx * ddx + ddy * ddy;

    float area1 = w1 * h1, area2 = w2 * h2;
    float uni = area1 + area2 - inter;
    out[i] = 1.0f - __fdividef(inter, uni) + __fdividef(d2, c2diag);
}

extern "C" void kernel_launch(void* const* d_in, const int* in_sizes, int n_in,
                              void* d_out, int out_size)
{
    const float* pred = (const float*)d_in[0];
    const float* tgt  = (const float*)d_in[1];
    float* out = (float*)d_out;
    int n = out_size;
    int threads = 256;
    int blocks = (n + threads - 1) / threads;
    riou_kernel<<<blocks, threads>>>(pred, tgt, out, n);
}

// round 9
// speedup vs baseline: 2.3538x; 2.3538x over previous
#include <cuda_runtime.h>
#include <math.h>

// Rotated-IoU loss, one thread per pair. Reference decision structure
// (validated at rel_err 4.96e-4 in R1/R6/R7). R9: local footprint cut from
// 320B to 192B/thread so per-SM local memory fits the L1 carveout:
//  - rank-count sort keys are order-preserving uint32 (one compare chain)
//  - inverse permutation packed as nibbles in ONE uint64 register (no s[16])
//  - shoelace walks ranks via nibble extracts, recomputing centered coords
//    with the reference's exact arithmetic and summation order.

__device__ __forceinline__ float pseudo_angle(float x, float y)
{
    float d = fabsf(x) + fabsf(y);
    float r = __fdividef(y, d);
    r = (d > 0.f) ? r : 0.f;
    return (x >= 0.f) ? r : ((y >= 0.f) ? 2.f - r : -2.f - r);
}

// monotone float -> uint32 (preserves total order of finite floats)
__device__ __forceinline__ unsigned int order_key(float a)
{
    unsigned int u = __float_as_uint(a);
    return (u & 0x80000000u) ? ~u : (u | 0x80000000u);
}

__global__ void __launch_bounds__(256)
riou_kernel(const float* __restrict__ pred,
            const float* __restrict__ tgt,
            float* __restrict__ out, int n)
{
    int i = blockIdx.x * blockDim.x + threadIdx.x;
    if (i >= n) return;

    const float2* pp = reinterpret_cast<const float2*>(pred) + (size_t)i * 3;
    const float2* tp = reinterpret_cast<const float2*>(tgt)  + (size_t)i * 3;
    float2 a0 = pp[0], a1 = pp[1], a2 = pp[2];
    float2 b0 = tp[0], b1 = tp[1], b2 = tp[2];

    const float x1c = a0.x, y1c = a0.y, w1 = a1.x, h1 = a1.y;
    const float x2c = b0.x, y2c = b0.y, w2 = b1.x, h2 = b1.y;

    float inv1 = rsqrtf(a2.x * a2.x + a2.y * a2.y);
    float s1 = a2.x * inv1, c1 = a2.y * inv1;
    float inv2 = rsqrtf(b2.x * b2.x + b2.y * b2.y);
    float s2 = b2.x * inv2, c2 = b2.y * inv2;

    const float dxv[4] = {0.5f, -0.5f, -0.5f, 0.5f};
    const float dyv[4] = {0.5f, 0.5f, -0.5f, -0.5f};
    float c1x[4], c1y[4], c2x[4], c2y[4];
#pragma unroll
    for (int j = 0; j < 4; j++) {
        float cx = dxv[j] * w1, cy = dyv[j] * h1;
        c1x[j] = cx * c1 - cy * s1 + x1c;
        c1y[j] = cx * s1 + cy * c1 + y1c;
    }
#pragma unroll
    for (int j = 0; j < 4; j++) {
        float cx = dxv[j] * w2, cy = dyv[j] * h2;
        c2x[j] = cx * c2 - cy * s2 + x2c;
        c2y[j] = cx * s2 + cy * c2 + y2c;
    }

    // ---- gather valid candidate vertices (compacted, reference order) ----
    float2 v[16];
    int    k = 0;
    float  sumx = 0.f, sumy = 0.f;
    const float eps = 1e-6f;

    {
        float ax = c2x[0], ay = c2y[0];
        float abx = c2x[1] - ax, aby = c2y[1] - ay;
        float adx = c2x[3] - ax, ady = c2y[3] - ay;
        float den_ab = abx * abx + aby * aby;
        float den_ad = adx * adx + ady * ady;
        float lo_ab = -eps * den_ab, hi_ab = (1.f + eps) * den_ab;
        float lo_ad = -eps * den_ad, hi_ad = (1.f + eps) * den_ad;
#pragma unroll
        for (int j = 0; j < 4; j++) {
            float amx = c1x[j] - ax, amy = c1y[j] - ay;
            float d_ab = abx * amx + aby * amy;
            float d_ad = adx * amx + ady * amy;
            if (d_ab > lo_ab && d_ab < hi_ab && d_ad > lo_ad && d_ad < hi_ad) {
                v[k] = make_float2(c1x[j], c1y[j]);
                sumx += c1x[j]; sumy += c1y[j];
                k++;
            }
        }
    }
    {
        float ax = c1x[0], ay = c1y[0];
        float abx = c1x[1] - ax, aby = c1y[1] - ay;
        float adx = c1x[3] - ax, ady = c1y[3] - ay;
        float den_ab = abx * abx + aby * aby;
        float den_ad = adx * adx + ady * ady;
        float lo_ab = -eps * den_ab, hi_ab = (1.f + eps) * den_ab;
        float lo_ad = -eps * den_ad, hi_ad = (1.f + eps) * den_ad;
#pragma unroll
        for (int j = 0; j < 4; j++) {
            float amx = c2x[j] - ax, amy = c2y[j] - ay;
            float d_ab = abx * amx + aby * amy;
            float d_ad = adx * amx + ady * amy;
            if (d_ab > lo_ab && d_ab < hi_ab && d_ad > lo_ad && d_ad < hi_ad) {
                v[k] = make_float2(c2x[j], c2y[j]);
                sumx += c2x[j]; sumy += c2y[j];
                k++;
            }
        }
    }
#pragma unroll
    for (int e1 = 0; e1 < 4; e1++) {
        float X1 = c1x[e1], Y1 = c1y[e1];
        float X2 = c1x[(e1 + 1) & 3], Y2 = c1y[(e1 + 1) & 3];
        float ex = X2 - X1, ey = Y2 - Y1;
#pragma unroll
        for (int e2 = 0; e2 < 4; e2++) {
            float X3 = c2x[e2], Y3 = c2y[e2];
            float X4 = c2x[(e2 + 1) & 3], Y4 = c2y[(e2 + 1) & 3];
            float gx = X4 - X3, gy = Y4 - Y3;
            float num_t = ex * (Y3 - Y1) - ey * (X3 - X1);
            float den   = ex * (Y3 - Y4) - ey * (X3 - X4);
            float num_u = gx * (Y1 - Y3) - gy * (X1 - X3);
            float den_u = -den;
            bool vt = (den > 0.f) ? (num_t > 0.f && num_t < den)
                                  : (den < 0.f && num_t < 0.f && num_t > den);
            bool vu = (den_u > 0.f) ? (num_u > 0.f && num_u < den_u)
                                    : (den_u < 0.f && num_u < 0.f && num_u > den_u);
            if (vt && vu) {
                float t = __fdividef(num_t, den);
                float ix = X1 + t * ex, iy = Y1 + t * ey;
                v[k] = make_float2(ix, iy);
                sumx += ix; sumy += iy;
                k++;
            }
        }
    }

    // ---- center + ordered-uint sort keys ----
    float invk = __fdividef(1.f, (float)(k > 0 ? k : 1));
    float meanx = sumx * invk, meany = sumy * invk;
    unsigned int ku[16];
    for (int j = 0; j < k; j++) {
        float vx = v[j].x - meanx, vy = v[j].y - meany;
        ku[j] = order_key(pseudo_angle(vx, vy));
    }

    // ---- rank-count; inverse permutation packed as nibbles in a u64 ----
    unsigned long long perm = 0ull;
    for (int ii = 0; ii < k; ii++) {
        unsigned int ki = ku[ii];
        int r = 0;
        for (int jj = 0; jj < k; jj++) {
            unsigned int kj = ku[jj];
            r += (int)((kj < ki) || (kj == ki && jj < ii));
        }
        perm |= (unsigned long long)(unsigned)ii << (4 * r);
    }

    // ---- shoelace: walk ranks via nibble extracts (reference order) ----
    float cr = 0.f;
    if (k > 0) {
        int idx0 = (int)(perm & 15ull);
        float2 f = v[idx0];
        float fx = f.x - meanx, fy = f.y - meany;
        float prx = fx, pry = fy;
        for (int j = 1; j < k; j++) {
            int idx = (int)((perm >> (4 * j)) & 15ull);
            float2 c = v[idx];
            float cx = c.x - meanx, cy = c.y - meany;
            cr += prx * cy - pry * cx;
            prx = cx; pry = cy;
        }
        cr += prx * fy - pry * fx;   // wrap: cross(s[k-1], s[0])
    }
    float inter = 0.5f * fabsf(cr);

    // ---- enclosing box + loss ----
    float xmin = c1x[0], xmax = c1x[0], ymin = c1y[0], ymax = c1y[0];
#pragma unroll
    for (int j = 1; j < 4; j++) {
        xmin = fminf(xmin, c1x[j]); xmax = fmaxf(xmax, c1x[j]);
        ymin = fminf(ymin, c1y[j]); ymax = fmaxf(ymax, c1y[j]);
    }
#pragma unroll
    for (int j = 0; j < 4; j++) {
        xmin = fminf(xmin, c2x[j]); xmax = fmaxf(xmax, c2x[j]);
        ymin = fminf(ymin, c2y[j]); ymax = fmaxf(ymax, c2y[j]);
    }
    float wc = xmax - xmin, hc = ymax - ymin;
    float c2diag = wc * wc + hc * hc;
    float ddx = x1c - x2c, ddy = y1c - y2c;
    float d2 = ddx * ddx + ddy * ddy;

    float area1 = w1 * h1, area2 = w2 * h2;
    float uni = area1 + area2 - inter;
    out[i] = 1.0f - __fdividef(inter, uni) + __fdividef(d2, c2diag);
}

extern "C" void kernel_launch(void* const* d_in, const int* in_sizes, int n_in,
                              void* d_out, int out_size)
{
    const float* pred = (const float*)d_in[0];
    const float* tgt  = (const float*)d_in[1];
    float* out = (float*)d_out;
    int n = out_size;
    int threads = 256;
    int blocks = (n + threads - 1) / threads;
    riou_kernel<<<blocks, threads>>>(pred, tgt, out, n);
}

// round 10
// speedup vs baseline: 2.8824x; 1.2246x over previous
#include <cuda_runtime.h>
#include <math.h>

// Rotated-IoU loss, one thread per pair. Reference decision structure
// (validated at rel_err 4.96e-4 in R1/R6/R7/R9). R10 ALU-diet:
//  - rank keys embed the tie-break index in low 4 bits -> ONE uint compare
//  - t/u masks via sign-product + |num|<|den| (exact equivalent, fma-pipe)
//  - 128-thread blocks for +occupancy (regs ~69 -> 7 CTAs/SM)

__device__ __forceinline__ float pseudo_angle(float x, float y)
{
    float d = fabsf(x) + fabsf(y);
    float r = __fdividef(y, d);
    r = (d > 0.f) ? r : 0.f;
    return (x >= 0.f) ? r : ((y >= 0.f) ? 2.f - r : -2.f - r);
}

// monotone float -> uint32 (preserves total order of finite floats)
__device__ __forceinline__ unsigned int order_key(float a)
{
    unsigned int u = __float_as_uint(a);
    return (u & 0x80000000u) ? ~u : (u | 0x80000000u);
}

__global__ void __launch_bounds__(128)
riou_kernel(const float* __restrict__ pred,
            const float* __restrict__ tgt,
            float* __restrict__ out, int n)
{
    int i = blockIdx.x * blockDim.x + threadIdx.x;
    if (i >= n) return;

    const float2* pp = reinterpret_cast<const float2*>(pred) + (size_t)i * 3;
    const float2* tp = reinterpret_cast<const float2*>(tgt)  + (size_t)i * 3;
    float2 a0 = pp[0], a1 = pp[1], a2 = pp[2];
    float2 b0 = tp[0], b1 = tp[1], b2 = tp[2];

    const float x1c = a0.x, y1c = a0.y, w1 = a1.x, h1 = a1.y;
    const float x2c = b0.x, y2c = b0.y, w2 = b1.x, h2 = b1.y;

    float inv1 = rsqrtf(a2.x * a2.x + a2.y * a2.y);
    float s1 = a2.x * inv1, c1 = a2.y * inv1;
    float inv2 = rsqrtf(b2.x * b2.x + b2.y * b2.y);
    float s2 = b2.x * inv2, c2 = b2.y * inv2;

    const float dxv[4] = {0.5f, -0.5f, -0.5f, 0.5f};
    const float dyv[4] = {0.5f, 0.5f, -0.5f, -0.5f};
    float c1x[4], c1y[4], c2x[4], c2y[4];
#pragma unroll
    for (int j = 0; j < 4; j++) {
        float cx = dxv[j] * w1, cy = dyv[j] * h1;
        c1x[j] = cx * c1 - cy * s1 + x1c;
        c1y[j] = cx * s1 + cy * c1 + y1c;
    }
#pragma unroll
    for (int j = 0; j < 4; j++) {
        float cx = dxv[j] * w2, cy = dyv[j] * h2;
        c2x[j] = cx * c2 - cy * s2 + x2c;
        c2y[j] = cx * s2 + cy * c2 + y2c;
    }

    // ---- gather valid candidate vertices (compacted, reference order) ----
    float2 v[16];
    int    k = 0;
    float  sumx = 0.f, sumy = 0.f;
    const float eps = 1e-6f;

    {
        float ax = c2x[0], ay = c2y[0];
        float abx = c2x[1] - ax, aby = c2y[1] - ay;
        float adx = c2x[3] - ax, ady = c2y[3] - ay;
        float den_ab = abx * abx + aby * aby;
        float den_ad = adx * adx + ady * ady;
        float lo_ab = -eps * den_ab, hi_ab = (1.f + eps) * den_ab;
        float lo_ad = -eps * den_ad, hi_ad = (1.f + eps) * den_ad;
#pragma unroll
        for (int j = 0; j < 4; j++) {
            float amx = c1x[j] - ax, amy = c1y[j] - ay;
            float d_ab = abx * amx + aby * amy;
            float d_ad = adx * amx + ady * amy;
            if (d_ab > lo_ab && d_ab < hi_ab && d_ad > lo_ad && d_ad < hi_ad) {
                v[k] = make_float2(c1x[j], c1y[j]);
                sumx += c1x[j]; sumy += c1y[j];
                k++;
            }
        }
    }
    {
        float ax = c1x[0], ay = c1y[0];
        float abx = c1x[1] - ax, aby = c1y[1] - ay;
        float adx = c1x[3] - ax, ady = c1y[3] - ay;
        float den_ab = abx * abx + aby * aby;
        float den_ad = adx * adx + ady * ady;
        float lo_ab = -eps * den_ab, hi_ab = (1.f + eps) * den_ab;
        float lo_ad = -eps * den_ad, hi_ad = (1.f + eps) * den_ad;
#pragma unroll
        for (int j = 0; j < 4; j++) {
            float amx = c2x[j] - ax, amy = c2y[j] - ay;
            float d_ab = abx * amx + aby * amy;
            float d_ad = adx * amx + ady * amy;
            if (d_ab > lo_ab && d_ab < hi_ab && d_ad > lo_ad && d_ad < hi_ad) {
                v[k] = make_float2(c2x[j], c2y[j]);
                sumx += c2x[j]; sumy += c2y[j];
                k++;
            }
        }
    }
    // edge intersections: t in (0,1) <=> num_t*den>0 && |num_t|<|den|
    //                     u in (0,1) <=> num_u*den<0 && |num_u|<|den|
    // (den_u = -den exactly; den==0 auto-fails both products)
#pragma unroll
    for (int e1 = 0; e1 < 4; e1++) {
        float X1 = c1x[e1], Y1 = c1y[e1];
        float X2 = c1x[(e1 + 1) & 3], Y2 = c1y[(e1 + 1) & 3];
        float ex = X2 - X1, ey = Y2 - Y1;
#pragma unroll
        for (int e2 = 0; e2 < 4; e2++) {
            float X3 = c2x[e2], Y3 = c2y[e2];
            float X4 = c2x[(e2 + 1) & 3], Y4 = c2y[(e2 + 1) & 3];
            float gx = X4 - X3, gy = Y4 - Y3;
            float num_t = ex * (Y3 - Y1) - ey * (X3 - X1);
            float den   = ex * (Y3 - Y4) - ey * (X3 - X4);
            float num_u = gx * (Y1 - Y3) - gy * (X1 - X3);
            float ad = fabsf(den);
            bool ok = (num_t * den > 0.f) & (fabsf(num_t) < ad)
                    & (num_u * den < 0.f) & (fabsf(num_u) < ad);
            if (ok) {
                float t = __fdividef(num_t, den);
                float ix = X1 + t * ex, iy = Y1 + t * ey;
                v[k] = make_float2(ix, iy);
                sumx += ix; sumy += iy;
                k++;
            }
        }
    }

    // ---- center + combined (angle,index) keys: ONE compare per pair ----
    float invk = __fdividef(1.f, (float)(k > 0 ? k : 1));
    float meanx = sumx * invk, meany = sumy * invk;
    unsigned int ku[16];
    for (int j = 0; j < k; j++) {
        float vx = v[j].x - meanx, vy = v[j].y - meany;
        ku[j] = (order_key(pseudo_angle(vx, vy)) & ~15u) | (unsigned)j;
    }

    // ---- rank-count; inverse permutation packed as nibbles in a u64 ----
    unsigned long long perm = 0ull;
    for (int ii = 0; ii < k; ii++) {
        unsigned int ki = ku[ii];
        int r = 0;
        for (int jj = 0; jj < k; jj++)
            r += (int)(ku[jj] < ki);
        perm |= (unsigned long long)(unsigned)ii << (4 * r);
    }

    // ---- shoelace: walk ranks via nibble extracts (reference order) ----
    float cr = 0.f;
    if (k > 0) {
        int idx0 = (int)(perm & 15ull);
        float2 f = v[idx0];
        float fx = f.x - meanx, fy = f.y - meany;
        float prx = fx, pry = fy;
        for (int j = 1; j < k; j++) {
            int idx = (int)((perm >> (4 * j)) & 15ull);
            float2 c = v[idx];
            float cx = c.x - meanx, cy = c.y - meany;
            cr += prx * cy - pry * cx;
            prx = cx; pry = cy;
        }
        cr += prx * fy - pry * fx;   // wrap: cross(s[k-1], s[0])
    }
    float inter = 0.5f * fabsf(cr);

    // ---- enclosing box + loss ----
    float xmin = c1x[0], xmax = c1x[0], ymin = c1y[0], ymax = c1y[0];
#pragma unroll
    for (int j = 1; j < 4; j++) {
        xmin = fminf(xmin, c1x[j]); xmax = fmaxf(xmax, c1x[j]);
        ymin = fminf(ymin, c1y[j]); ymax = fmaxf(ymax, c1y[j]);
    }
#pragma unroll
    for (int j = 0; j < 4; j++) {
        xmin = fminf(xmin, c2x[j]); xmax = fmaxf(xmax, c2x[j]);
        ymin = fminf(ymin, c2y[j]); ymax = fmaxf(ymax, c2y[j]);
    }
    float wc = xmax - xmin, hc = ymax - ymin;
    float c2diag = wc * wc + hc * hc;
    float ddx = x1c - x2c, ddy = y1c - y2c;
    float d2 = ddx * ddx + ddy * ddy;

    float area1 = w1 * h1, area2 = w2 * h2;
    float uni = area1 + area2 - inter;
    out[i] = 1.0f - __fdividef(inter, uni) + __fdividef(d2, c2diag);
}

extern "C" void kernel_launch(void* const* d_in, const int* in_sizes, int n_in,
                              void* d_out, int out_size)
{
    const float* pred = (const float*)d_in[0];
    const float* tgt  = (const float*)d_in[1];
    float* out = (float*)d_out;
    int n = out_size;
    int threads = 128;
    int blocks = (n + threads - 1) / threads;
    riou_kernel<<<blocks, threads>>>(pred, tgt, out, n);
}

// round 11
// speedup vs baseline: 2.9762x; 1.0325x over previous
#include <cuda_runtime.h>
#include <math.h>

// Rotated-IoU loss, one thread per pair. Reference decision structure
// (validated rel_err 4.96e-4 across R1/R6/R7/R9/R10). R11 instruction diet:
//  - edge loop: per-e1/per-e2 invariants hoisted (num_t/den/num_u in 3/2/3 ops)
//  - corner tests: dot-product bases precomputed
//  - dynamic loops unrolled x4 (loop overhead was ~40% of rank-loop work)
//  - shoelace walks the packed permutation with a running >>4

__device__ __forceinline__ float pseudo_angle(float x, float y)
{
    float d = fabsf(x) + fabsf(y);
    float r = __fdividef(y, d);
    r = (d > 0.f) ? r : 0.f;
    return (x >= 0.f) ? r : ((y >= 0.f) ? 2.f - r : -2.f - r);
}

__device__ __forceinline__ unsigned int order_key(float a)
{
    unsigned int u = __float_as_uint(a);
    return (u & 0x80000000u) ? ~u : (u | 0x80000000u);
}

__global__ void __launch_bounds__(128)
riou_kernel(const float* __restrict__ pred,
            const float* __restrict__ tgt,
            float* __restrict__ out, int n)
{
    int i = blockIdx.x * blockDim.x + threadIdx.x;
    if (i >= n) return;

    const float2* pp = reinterpret_cast<const float2*>(pred) + (size_t)i * 3;
    const float2* tp = reinterpret_cast<const float2*>(tgt)  + (size_t)i * 3;
    float2 a0 = pp[0], a1 = pp[1], a2 = pp[2];
    float2 b0 = tp[0], b1 = tp[1], b2 = tp[2];

    const float x1c = a0.x, y1c = a0.y, w1 = a1.x, h1 = a1.y;
    const float x2c = b0.x, y2c = b0.y, w2 = b1.x, h2 = b1.y;

    float inv1 = rsqrtf(a2.x * a2.x + a2.y * a2.y);
    float s1 = a2.x * inv1, c1 = a2.y * inv1;
    float inv2 = rsqrtf(b2.x * b2.x + b2.y * b2.y);
    float s2 = b2.x * inv2, c2 = b2.y * inv2;

    const float dxv[4] = {0.5f, -0.5f, -0.5f, 0.5f};
    const float dyv[4] = {0.5f, 0.5f, -0.5f, -0.5f};
    float c1x[4], c1y[4], c2x[4], c2y[4];
#pragma unroll
    for (int j = 0; j < 4; j++) {
        float cx = dxv[j] * w1, cy = dyv[j] * h1;
        c1x[j] = cx * c1 - cy * s1 + x1c;
        c1y[j] = cx * s1 + cy * c1 + y1c;
    }
#pragma unroll
    for (int j = 0; j < 4; j++) {
        float cx = dxv[j] * w2, cy = dyv[j] * h2;
        c2x[j] = cx * c2 - cy * s2 + x2c;
        c2y[j] = cx * s2 + cy * c2 + y2c;
    }

    // ---- gather valid candidate vertices (compacted, reference order) ----
    float2 v[16];
    int    k = 0;
    float  sumx = 0.f, sumy = 0.f;
    const float eps = 1e-6f;

    // corners of box1 inside box2
    {
        float ax = c2x[0], ay = c2y[0];
        float abx = c2x[1] - ax, aby = c2y[1] - ay;
        float adx = c2x[3] - ax, ady = c2y[3] - ay;
        float den_ab = abx * abx + aby * aby;
        float den_ad = adx * adx + ady * ady;
        float base_ab = abx * ax + aby * ay;
        float base_ad = adx * ax + ady * ay;
        float lo_ab = -eps * den_ab, hi_ab = (1.f + eps) * den_ab;
        float lo_ad = -eps * den_ad, hi_ad = (1.f + eps) * den_ad;
#pragma unroll
        for (int j = 0; j < 4; j++) {
            float d_ab = abx * c1x[j] + aby * c1y[j] - base_ab;
            float d_ad = adx * c1x[j] + ady * c1y[j] - base_ad;
            if (d_ab > lo_ab && d_ab < hi_ab && d_ad > lo_ad && d_ad < hi_ad) {
                v[k] = make_float2(c1x[j], c1y[j]);
                sumx += c1x[j]; sumy += c1y[j];
                k++;
            }
        }
    }
    // corners of box2 inside box1
    {
        float ax = c1x[0], ay = c1y[0];
        float abx = c1x[1] - ax, aby = c1y[1] - ay;
        float adx = c1x[3] - ax, ady = c1y[3] - ay;
        float den_ab = abx * abx + aby * aby;
        float den_ad = adx * adx + ady * ady;
        float base_ab = abx * ax + aby * ay;
        float base_ad = adx * ax + ady * ay;
        float lo_ab = -eps * den_ab, hi_ab = (1.f + eps) * den_ab;
        float lo_ad = -eps * den_ad, hi_ad = (1.f + eps) * den_ad;
#pragma unroll
        for (int j = 0; j < 4; j++) {
            float d_ab = abx * c2x[j] + aby * c2y[j] - base_ab;
            float d_ad = adx * c2x[j] + ady * c2y[j] - base_ad;
            if (d_ab > lo_ab && d_ab < hi_ab && d_ad > lo_ad && d_ad < hi_ad) {
                v[k] = make_float2(c2x[j], c2y[j]);
                sumx += c2x[j]; sumy += c2y[j];
                k++;
            }
        }
    }

    // ---- 4x4 edge intersections, invariants hoisted ----
    // t in (0,1) <=> num_t*den>0 && |num_t|<|den|
    // u in (0,1) <=> num_u*den<0 && |num_u|<|den|   (den_u = -den exactly)
    float gxv[4], gyv[4], hq[4];
#pragma unroll
    for (int e2 = 0; e2 < 4; e2++) {
        int e2n = (e2 + 1) & 3;
        float gx = c2x[e2n] - c2x[e2];
        float gy = c2y[e2n] - c2y[e2];
        gxv[e2] = gx; gyv[e2] = gy;
        hq[e2] = gx * c2y[e2] - gy * c2x[e2];   // gx*Y3 - gy*X3
    }
#pragma unroll
    for (int e1 = 0; e1 < 4; e1++) {
        float X1 = c1x[e1], Y1 = c1y[e1];
        float ex = c1x[(e1 + 1) & 3] - X1, ey = c1y[(e1 + 1) & 3] - Y1;
        float hp = ex * Y1 - ey * X1;           // ex*Y1 - ey*X1
#pragma unroll
        for (int e2 = 0; e2 < 4; e2++) {
            float gx = gxv[e2], gy = gyv[e2];
            float X3 = c2x[e2], Y3 = c2y[e2];
            float num_t = ex * Y3 - ey * X3 - hp;
            float den   = ey * gx - ex * gy;
            float num_u = gx * Y1 - gy * X1 - hq[e2];
            float ad = fabsf(den);
            bool ok = (num_t * den > 0.f) & (fabsf(num_t) < ad)
                    & (num_u * den < 0.f) & (fabsf(num_u) < ad);
            if (ok) {
                float t = __fdividef(num_t, den);
                float ix = X1 + t * ex, iy = Y1 + t * ey;
                v[k] = make_float2(ix, iy);
                sumx += ix; sumy += iy;
                k++;
            }
        }
    }

    // ---- center + combined (angle,index) keys ----
    float invk = __fdividef(1.f, (float)(k > 0 ? k : 1));
    float meanx = sumx * invk, meany = sumy * invk;
    unsigned int ku[16];
#pragma unroll 4
    for (int j = 0; j < k; j++) {
        float vx = v[j].x - meanx, vy = v[j].y - meany;
        ku[j] = (order_key(pseudo_angle(vx, vy)) & ~15u) | (unsigned)j;
    }

    // ---- rank-count; inverse permutation packed as nibbles in a u64 ----
    unsigned long long perm = 0ull;
    for (int ii = 0; ii < k; ii++) {
        unsigned int ki = ku[ii];
        int r = 0;
#pragma unroll 4
        for (int jj = 0; jj < k; jj++)
            r += (int)(ku[jj] < ki);
        perm |= (unsigned long long)(unsigned)ii << (4 * r);
    }

    // ---- shoelace: walk ranks (reference order), running shift ----
    float cr = 0.f;
    if (k > 0) {
        int idx0 = (int)(perm & 15ull);
        float2 f = v[idx0];
        float fx = f.x - meanx, fy = f.y - meany;
        float prx = fx, pry = fy;
        unsigned long long pw = perm >> 4;
#pragma unroll 4
        for (int j = 1; j < k; j++) {
            int idx = (int)(pw & 15ull);
            pw >>= 4;
            float2 c = v[idx];
            float cx = c.x - meanx, cy = c.y - meany;
            cr += prx * cy - pry * cx;
            prx = cx; pry = cy;
        }
        cr += prx * fy - pry * fx;   // wrap: cross(s[k-1], s[0])
    }
    float inter = 0.5f * fabsf(cr);

    // ---- enclosing box + loss ----
    float xmin = c1x[0], xmax = c1x[0], ymin = c1y[0], ymax = c1y[0];
#pragma unroll
    for (int j = 1; j < 4; j++) {
        xmin = fminf(xmin, c1x[j]); xmax = fmaxf(xmax, c1x[j]);
        ymin = fminf(ymin, c1y[j]); ymax = fmaxf(ymax, c1y[j]);
    }
#pragma unroll
    for (int j = 0; j < 4; j++) {
        xmin = fminf(xmin, c2x[j]); xmax = fmaxf(xmax, c2x[j]);
        ymin = fminf(ymin, c2y[j]); ymax = fmaxf(ymax, c2y[j]);
    }
    float wc = xmax - xmin, hc = ymax - ymin;
    float c2diag = wc * wc + hc * hc;
    float ddx = x1c - x2c, ddy = y1c - y2c;
    float d2 = ddx * ddx + ddy * ddy;

    float area1 = w1 * h1, area2 = w2 * h2;
    float uni = area1 + area2 - inter;
    out[i] = 1.0f - __fdividef(inter, uni) + __fdividef(d2, c2diag);
}

extern "C" void kernel_launch(void* const* d_in, const int* in_sizes, int n_in,
                              void* d_out, int out_size)
{
    const float* pred = (const float*)d_in[0];
    const float* tgt  = (const float*)d_in[1];
    float* out = (float*)d_out;
    int n = out_size;
    int threads = 128;
    int blocks = (n + threads - 1) / threads;
    riou_kernel<<<blocks, threads>>>(pred, tgt, out, n);
}